// round 13
// baseline (speedup 1.0000x reference)
#include <cuda_runtime.h>
#include <cuda_fp16.h>
#include <cstdint>

#define N_NODES 100000
#define N_PAD   100096          // multiple of 128 for fused gemm tiles
#define N_EDGES 1600000
#define IN_DIM 128
#define HIDDEN 128
#define OUT_DIM 64

#define SCAN_TILES 196          // ceil(100000/512)
#define N_TILES (N_PAD / 128)   // 782
#define MMA_GRID 296            // 2 CTAs/SM * 148 SMs

typedef unsigned long long ull;
typedef unsigned int u32;

// -------- scratch (static device globals; no allocation allowed) --------
__device__ __align__(16) __half g_xh[(size_t)N_NODES * IN_DIM];   // x in fp16
__device__ __align__(16) __half g_axh[(size_t)N_PAD * IN_DIM];    // A_norm @ x, fp16
__device__ __align__(16) __half g_w1h[IN_DIM * HIDDEN];
__device__ __align__(16) __half g_w2h[HIDDEN * OUT_DIM];
__device__ float g_dinv[N_NODES];
// zero blob: [0, N_NODES) = per-node incoming counts ; [N_NODES, +256) = scan status
__device__ int   g_zero_blob[N_NODES + 256];
__device__ int   g_off[N_NODES];
__device__ int   g_cur[N_NODES];
__device__ __align__(16) uint2 g_epack[N_EDGES];   // {src, dinv[src] bits}

#define CNT(i)    (g_zero_blob[i])
#define STATUS(t) (((u32*)g_zero_blob)[N_NODES + (t)])
#define FLAG_AGG 0x40000000u
#define FLAG_INC 0x80000000u
#define VALMASK  0x3FFFFFFFu

// -------- mma / ldmatrix / cp.async helpers --------
#define LDSM4(a0,a1,a2,a3,addr) \
    asm volatile("ldmatrix.sync.aligned.m8n8.x4.shared.b16 {%0,%1,%2,%3},[%4];" \
                 : "=r"(a0),"=r"(a1),"=r"(a2),"=r"(a3) : "r"(addr))
#define LDSM2T(b0,b1,addr) \
    asm volatile("ldmatrix.sync.aligned.m8n8.x2.trans.shared.b16 {%0,%1},[%2];" \
                 : "=r"(b0),"=r"(b1) : "r"(addr))
#define MMA16816(d,a0,a1,a2,a3,b0,b1) \
    asm volatile("mma.sync.aligned.m16n8k16.row.col.f32.f16.f16.f32 " \
                 "{%0,%1,%2,%3},{%4,%5,%6,%7},{%8,%9},{%0,%1,%2,%3};" \
                 : "+f"((d)[0]),"+f"((d)[1]),"+f"((d)[2]),"+f"((d)[3]) \
                 : "r"(a0),"r"(a1),"r"(a2),"r"(a3),"r"(b0),"r"(b1))
#define CP_ASYNC16(saddr, gptr) \
    asm volatile("cp.async.cg.shared.global [%0], [%1], 16;" :: "r"(saddr), "l"(gptr))
#define CP_ASYNC_COMMIT() asm volatile("cp.async.commit_group;")
#define CP_ASYNC_WAIT0()  asm volatile("cp.async.wait_group 0;")

__device__ __forceinline__ u32 smaddr(const void* p) {
    return (u32)__cvta_generic_to_shared(p);
}

__device__ __forceinline__ int edge_idx(const void* ei, long long elem, int is64) {
    if (is64) return (int)((const long long*)ei)[elem];
    return ((const int*)ei)[elem];
}

// block-local edge dtype detection (first 256 u64 words; int64 -> all-zero high words)
__device__ __forceinline__ int detect_is64_block(const void* ei) {
    const ull* p = (const ull*)ei;
    int any = __syncthreads_or((int)((p[threadIdx.x & 255] >> 32) != 0ULL));
    return !any;
}

__device__ __forceinline__ void f4_to_h8(float4 v, uint2& o) {
    __half2 h01 = __floats2half2_rn(v.x, v.y);
    __half2 h23 = __floats2half2_rn(v.z, v.w);
    o.x = *(const u32*)&h01;
    o.y = *(const u32*)&h23;
}

// ============ prep (fat kernel): convert x | convert W | count degrees ========
__global__ void __launch_bounds__(256) prep_kernel(const float* __restrict__ x,
                                                   const float* __restrict__ W1,
                                                   const float* __restrict__ W2,
                                                   const void* __restrict__ ei) {
    int b = blockIdx.x, tid = threadIdx.x;
    if (b < 3125) {
        const float4* X4 = (const float4*)x;
#pragma unroll
        for (int j = 0; j < 4; j++) {
            int i = b * 1024 + tid + 256 * j;
            uint2 o; f4_to_h8(X4[i], o);
            ((uint2*)g_xh)[i] = o;
        }
    } else if (b < 3149) {
        int i = (b - 3125) * 256 + tid;          // [0, 6144)
        if (i < 4096) {
            uint2 o; f4_to_h8(((const float4*)W1)[i], o);
            ((uint2*)g_w1h)[i] = o;
        } else {
            int j = i - 4096;                    // [0, 2048)
            uint2 o; f4_to_h8(((const float4*)W2)[j], o);
            ((uint2*)g_w2h)[j] = o;
        }
    } else {
        int is64 = detect_is64_block(ei);
        int e = (b - 3149) * 256 + tid;          // < 1.6M exactly
        int d = edge_idx(ei, (long long)N_EDGES + e, is64);
        atomicAdd(&CNT(d), 1);
    }
}

// ============ single-pass scan (decoupled lookback) + dinv + cur ==============
__device__ __forceinline__ u32 warp_sum_u32(u32 v) {
    v += __shfl_xor_sync(~0u, v, 16);
    v += __shfl_xor_sync(~0u, v, 8);
    v += __shfl_xor_sync(~0u, v, 4);
    v += __shfl_xor_sync(~0u, v, 2);
    v += __shfl_xor_sync(~0u, v, 1);
    return v;
}

__global__ void __launch_bounds__(512) scan_fused_kernel() {
    __shared__ int wsum[16];
    __shared__ int s_prefix;
    int tile = blockIdx.x, tid = threadIdx.x;
    int lane = tid & 31, w = tid >> 5;
    int i = tile * 512 + tid;
    int v = (i < N_NODES) ? CNT(i) : 0;

    int xv = v;
#pragma unroll
    for (int d = 1; d < 32; d <<= 1) {
        int y = __shfl_up_sync(~0u, xv, d);
        if (lane >= d) xv += y;
    }
    if (lane == 31) wsum[w] = xv;
    __syncthreads();
    if (w == 0) {
        int s = (lane < 16) ? wsum[lane] : 0;
#pragma unroll
        for (int d = 1; d < 16; d <<= 1) {
            int y = __shfl_up_sync(~0u, s, d);
            if (lane >= d) s += y;
        }
        if (lane < 16) wsum[lane] = s;
    }
    __syncthreads();
    int warp_off = w ? wsum[w - 1] : 0;
    int incl = xv + warp_off;
    int total = wsum[15];

    if (w == 0) {
        if (lane == 0)
            atomicExch(&STATUS(tile), (u32)total | (tile == 0 ? FLAG_INC : FLAG_AGG));
        u32 prefix = 0;
        if (tile > 0) {
            int t = tile - 1;
            while (true) {
                int idx = t - lane;
                u32 s = (idx >= 0) ? atomicAdd(&STATUS(idx), 0u) : FLAG_INC;
                if (__ballot_sync(~0u, (s & 0xC0000000u) != 0u) != 0xFFFFFFFFu) continue;
                u32 incmask = __ballot_sync(~0u, (s & FLAG_INC) != 0u);
                if (incmask == 0u) {
                    prefix += warp_sum_u32(s & VALMASK);
                    t -= 32;
                } else {
                    int firstinc = __ffs(incmask) - 1;
                    u32 contrib = (lane <= firstinc) ? (s & VALMASK) : 0u;
                    prefix += warp_sum_u32(contrib);
                    break;
                }
            }
            if (lane == 0) atomicExch(&STATUS(tile), (prefix + (u32)total) | FLAG_INC);
        }
        if (lane == 0) s_prefix = (int)prefix;
    }
    __syncthreads();
    if (i < N_NODES) {
        int off = s_prefix + incl - v;
        g_off[i] = off;
        g_cur[i] = off;
        g_dinv[i] = rsqrtf((float)(v + 1));   // +1 self-loop
    }
}

// ============ bucket edges by dst: write {src, dinv[src] bits} ===============
__global__ void __launch_bounds__(256) bucket_kernel(const void* __restrict__ ei) {
    int is64 = detect_is64_block(ei);
    int e = blockIdx.x * 256 + threadIdx.x;   // < 1.6M exactly
    int s = edge_idx(ei, e, is64);
    int d = edge_idx(ei, (long long)N_EDGES + e, is64);
    float ns = __ldg(g_dinv + s);
    int pos = atomicAdd(&g_cur[d], 1);
    uint2 en; en.x = (u32)s; en.y = __float_as_uint(ns);
    g_epack[pos] = en;
}

// ============ aggregate: half-warp per node, uint4 gathers (1 LDG/edge) ======
__device__ __forceinline__ void acc_half16(float* acc, uint4 v, float n) {
    float2 f0 = __half22float2(*(__half2*)&v.x);
    float2 f1 = __half22float2(*(__half2*)&v.y);
    float2 f2 = __half22float2(*(__half2*)&v.z);
    float2 f3 = __half22float2(*(__half2*)&v.w);
    acc[0] += n * f0.x; acc[1] += n * f0.y;
    acc[2] += n * f1.x; acc[3] += n * f1.y;
    acc[4] += n * f2.x; acc[5] += n * f2.y;
    acc[6] += n * f3.x; acc[7] += n * f3.y;
}

__global__ void __launch_bounds__(256) aggregate_kernel() {
    int warp = threadIdx.x >> 5, lane = threadIdx.x & 31;
    int h = lane >> 4, sl = lane & 15;
    int node = blockIdx.x * 16 + warp * 2 + h;   // grid covers N_PAD/16 blocks

    int beg = 0, len = 0;
    float dd = 0.f;
    if (node < N_NODES) {
        beg = g_off[node];
        int end = (node + 1 < N_NODES) ? g_off[node + 1] : N_EDGES;
        len = end - beg;
        dd = g_dinv[node];
    }

    float acc[8];
#pragma unroll
    for (int j = 0; j < 8; j++) acc[j] = 0.f;

    // self-loop (dd = 0 for pad nodes -> contributes 0; row 0 used as safe addr)
    int srow = (node < N_NODES) ? node : 0;
    uint4 sv = __ldg(((const uint4*)g_xh) + (size_t)srow * 16 + sl);
    acc_half16(acc, sv, dd * dd);

    int lmax = len;
    {
        int other = __shfl_xor_sync(~0u, len, 16);
        if (other > lmax) lmax = other;
    }

    int k = 0;
    for (; k + 1 < lmax; k += 2) {
        bool p0 = (k < len), p1 = (k + 1 < len);
        uint2 e0 = p0 ? __ldg(g_epack + beg + k)     : make_uint2(0u, 0u);
        uint2 e1 = p1 ? __ldg(g_epack + beg + k + 1) : make_uint2(0u, 0u);
        float n0 = p0 ? __uint_as_float(e0.y) * dd : 0.f;
        float n1 = p1 ? __uint_as_float(e1.y) * dd : 0.f;
        uint4 v0 = __ldg(((const uint4*)g_xh) + (size_t)e0.x * 16 + sl);
        uint4 v1 = __ldg(((const uint4*)g_xh) + (size_t)e1.x * 16 + sl);
        acc_half16(acc, v0, n0);
        acc_half16(acc, v1, n1);
    }
    if (k < lmax) {
        bool p0 = (k < len);
        uint2 e0 = p0 ? __ldg(g_epack + beg + k) : make_uint2(0u, 0u);
        float n0 = p0 ? __uint_as_float(e0.y) * dd : 0.f;
        uint4 v0 = __ldg(((const uint4*)g_xh) + (size_t)e0.x * 16 + sl);
        acc_half16(acc, v0, n0);
    }

    __half2 h0 = __floats2half2_rn(acc[0], acc[1]);
    __half2 h1 = __floats2half2_rn(acc[2], acc[3]);
    __half2 h2 = __floats2half2_rn(acc[4], acc[5]);
    __half2 h3 = __floats2half2_rn(acc[6], acc[7]);
    uint4 o;
    o.x = *(const u32*)&h0;
    o.y = *(const u32*)&h1;
    o.z = *(const u32*)&h2;
    o.w = *(const u32*)&h3;
    ((uint4*)g_axh)[(size_t)node * 16 + sl] = o;   // node < N_PAD always
}

// -------- persistent fused tensor-core GEMM ---------------------------------
#define AS 136   // padded row stride (halfs) for 128-wide tiles
#define WS2 72   // padded row stride for 64-wide W2 tile

__global__ void __launch_bounds__(512, 2) fused_mma_kernel(const float* __restrict__ b1,
                                                           const float* __restrict__ b2,
                                                           float* __restrict__ out) {
    extern __shared__ __half smh[];
    __half* sW1 = smh;                 // 128 x AS
    __half* sW2 = sW1 + 128 * AS;      // 128 x WS2
    __half* sA  = sW2 + 128 * WS2;     // 128 x AS  (reused as T tile)
    __half* sT  = sA;                  // alias

    int tid = threadIdx.x;
    int warp = tid >> 5, lane = tid & 31;
    int nr = (warp & 7) * 16;
    int colq = 2 * (lane & 3);
    int rq = lane >> 2;

    // ---- load W tiles once ----
    {
        const uint4* W14 = (const uint4*)g_w1h;
#pragma unroll
        for (int i = 0; i < 4; i++) {
            int idx = tid + 512 * i;
            int row = idx >> 4, c = idx & 15;
            CP_ASYNC16(smaddr(sW1 + row * AS + c * 8), W14 + idx);
        }
        const uint4* W24 = (const uint4*)g_w2h;
#pragma unroll
        for (int i = 0; i < 2; i++) {
            int idx = tid + 512 * i;
            int row = idx >> 3, c = idx & 7;
            CP_ASYNC16(smaddr(sW2 + row * WS2 + c * 8), W24 + idx);
        }
        CP_ASYNC_COMMIT();
    }

    for (int tile = blockIdx.x; tile < N_TILES; tile += MMA_GRID) {
        int base = tile * 128;

        {
            const uint4* A4 = (const uint4*)(g_axh + (size_t)base * 128);
#pragma unroll
            for (int i = 0; i < 4; i++) {
                int idx = tid + 512 * i;
                int row = idx >> 4, c = idx & 15;
                CP_ASYNC16(smaddr(sA + row * AS + c * 8), A4 + idx);
            }
            CP_ASYNC_COMMIT();
            CP_ASYNC_WAIT0();
        }
        __syncthreads();

        // ---- stage 1: acc = sA @ W1 ----
        float acc1[8][4];
        {
            int cb = (warp >> 3) * 64;
#pragma unroll
            for (int t = 0; t < 8; t++)
#pragma unroll
                for (int j = 0; j < 4; j++) acc1[t][j] = 0.f;

            u32 aAbase = smaddr(sA + (nr + (lane & 15)) * AS + ((lane >> 4) * 8));
            u32 aBbase = smaddr(sW1 + (lane & 15) * AS + cb);

#pragma unroll
            for (int ks = 0; ks < 8; ks++) {
                u32 a0, a1, a2, a3;
                LDSM4(a0, a1, a2, a3, aAbase + ks * 32);
#pragma unroll
                for (int nt = 0; nt < 8; nt++) {
                    u32 b0, b1r;
                    LDSM2T(b0, b1r, aBbase + ks * 16 * AS * 2 + nt * 16);
                    MMA16816(acc1[nt], a0, a1, a2, a3, b0, b1r);
                }
            }
        }
        __syncthreads();   // all stage-1 reads of sA complete

        // ---- epilogue 1: T = relu(acc + b1) written over sA ----
        {
            int cb = (warp >> 3) * 64;
#pragma unroll
            for (int nt = 0; nt < 8; nt++) {
                int c0 = cb + nt * 8 + colq;
                float2 bv = __ldg((const float2*)(b1 + c0));
                int r0 = nr + rq;
                __half2 h0 = __floats2half2_rn(fmaxf(acc1[nt][0] + bv.x, 0.f),
                                               fmaxf(acc1[nt][1] + bv.y, 0.f));
                __half2 h1 = __floats2half2_rn(fmaxf(acc1[nt][2] + bv.x, 0.f),
                                               fmaxf(acc1[nt][3] + bv.y, 0.f));
                *(__half2*)(sT + r0 * AS + c0) = h0;
                *(__half2*)(sT + (r0 + 8) * AS + c0) = h1;
            }
        }
        __syncthreads();

        // ---- stage 2: out = T @ W2 + b2 ----
        {
            int cb = (warp >> 3) * 32;
            float acc[4][4];
#pragma unroll
            for (int t = 0; t < 4; t++)
#pragma unroll
                for (int j = 0; j < 4; j++) acc[t][j] = 0.f;

            u32 aAbase = smaddr(sT + (nr + (lane & 15)) * AS + ((lane >> 4) * 8));
            u32 aBbase = smaddr(sW2 + (lane & 15) * WS2 + cb);

#pragma unroll
            for (int ks = 0; ks < 8; ks++) {
                u32 a0, a1, a2, a3;
                LDSM4(a0, a1, a2, a3, aAbase + ks * 32);
#pragma unroll
                for (int nt = 0; nt < 4; nt++) {
                    u32 b0, b1r;
                    LDSM2T(b0, b1r, aBbase + ks * 16 * WS2 * 2 + nt * 16);
                    MMA16816(acc[nt], a0, a1, a2, a3, b0, b1r);
                }
            }

#pragma unroll
            for (int nt = 0; nt < 4; nt++) {
                int c0 = cb + nt * 8 + colq;
                float2 bv = __ldg((const float2*)(b2 + c0));
                int n0 = base + nr + rq;
                int n1 = n0 + 8;
                if (n0 < N_NODES) {
                    float2 r = make_float2(acc[nt][0] + bv.x, acc[nt][1] + bv.y);
                    *(float2*)(out + (size_t)n0 * OUT_DIM + c0) = r;
                }
                if (n1 < N_NODES) {
                    float2 r = make_float2(acc[nt][2] + bv.x, acc[nt][3] + bv.y);
                    *(float2*)(out + (size_t)n1 * OUT_DIM + c0) = r;
                }
            }
        }
        __syncthreads();   // stage-2 reads of sT done before next tile overwrites sA
    }
}

extern "C" void kernel_launch(void* const* d_in, const int* in_sizes, int n_in,
                              void* d_out, int out_size) {
    const float* x  = (const float*)d_in[0];
    const float* W1 = (const float*)d_in[1];
    const float* b1 = (const float*)d_in[2];
    const float* W2 = (const float*)d_in[3];
    const float* b2 = (const float*)d_in[4];
    const void*  ei = d_in[5];
    float* out = (float*)d_out;

    const int FUSED_SMEM = (2 * 128 * AS + 128 * WS2) * 2;   // 88064 B
    cudaFuncSetAttribute(fused_mma_kernel, cudaFuncAttributeMaxDynamicSharedMemorySize, FUSED_SMEM);

    void* zero_ptr = nullptr;
    cudaGetSymbolAddress(&zero_ptr, g_zero_blob);
    cudaMemsetAsync(zero_ptr, 0, (N_NODES + 256) * sizeof(int));

    prep_kernel<<<3125 + 24 + 6250, 256>>>(x, W1, W2, ei);
    scan_fused_kernel<<<SCAN_TILES, 512>>>();
    bucket_kernel<<<N_EDGES / 256, 256>>>(ei);
    aggregate_kernel<<<N_PAD / 16, 256>>>();
    fused_mma_kernel<<<MMA_GRID, 512, FUSED_SMEM>>>(b1, b2, out);
}

// round 14
// speedup vs baseline: 1.0333x; 1.0333x over previous
#include <cuda_runtime.h>
#include <cuda_fp16.h>
#include <cstdint>

#define N_NODES 100000
#define N_PAD   100096          // multiple of 128 for fused gemm tiles
#define N_EDGES 1600000
#define IN_DIM 128
#define HIDDEN 128
#define OUT_DIM 64

#define SCAN_TILES 196          // ceil(100000/512)
#define N_TILES (N_PAD / 128)   // 782
#define MMA_GRID 296            // 2 CTAs/SM * 148 SMs

typedef unsigned long long ull;
typedef unsigned int u32;

// -------- scratch (static device globals; no allocation allowed) --------
__device__ __align__(16) __half g_xh[(size_t)N_NODES * IN_DIM];   // x in fp16
__device__ __align__(16) __half g_axh[(size_t)N_PAD * IN_DIM];    // A_norm @ x, fp16
__device__ __align__(16) __half g_w1h[IN_DIM * HIDDEN];
__device__ __align__(16) __half g_w2h[HIDDEN * OUT_DIM];
__device__ float g_dinv[N_NODES];
// zero blob: [0, N_NODES) = per-node incoming counts ; [N_NODES, +256) = scan status
__device__ int   g_zero_blob[N_NODES + 256];
__device__ int   g_off[N_NODES];
__device__ int   g_cur[N_NODES];
__device__ __align__(16) uint2 g_epack[N_EDGES];   // {src, dinv[src] bits}

#define CNT(i)    (g_zero_blob[i])
#define STATUS(t) (((u32*)g_zero_blob)[N_NODES + (t)])
#define FLAG_AGG 0x40000000u
#define FLAG_INC 0x80000000u
#define VALMASK  0x3FFFFFFFu

// -------- mma / ldmatrix / cp.async helpers --------
#define LDSM4(a0,a1,a2,a3,addr) \
    asm volatile("ldmatrix.sync.aligned.m8n8.x4.shared.b16 {%0,%1,%2,%3},[%4];" \
                 : "=r"(a0),"=r"(a1),"=r"(a2),"=r"(a3) : "r"(addr))
#define LDSM2T(b0,b1,addr) \
    asm volatile("ldmatrix.sync.aligned.m8n8.x2.trans.shared.b16 {%0,%1},[%2];" \
                 : "=r"(b0),"=r"(b1) : "r"(addr))
#define MMA16816(d,a0,a1,a2,a3,b0,b1) \
    asm volatile("mma.sync.aligned.m16n8k16.row.col.f32.f16.f16.f32 " \
                 "{%0,%1,%2,%3},{%4,%5,%6,%7},{%8,%9},{%0,%1,%2,%3};" \
                 : "+f"((d)[0]),"+f"((d)[1]),"+f"((d)[2]),"+f"((d)[3]) \
                 : "r"(a0),"r"(a1),"r"(a2),"r"(a3),"r"(b0),"r"(b1))
#define CP_ASYNC16(saddr, gptr) \
    asm volatile("cp.async.cg.shared.global [%0], [%1], 16;" :: "r"(saddr), "l"(gptr))
#define CP_ASYNC_COMMIT() asm volatile("cp.async.commit_group;")
#define CP_ASYNC_WAIT0()  asm volatile("cp.async.wait_group 0;")

__device__ __forceinline__ u32 smaddr(const void* p) {
    return (u32)__cvta_generic_to_shared(p);
}

__device__ __forceinline__ int edge_idx(const void* ei, long long elem, int is64) {
    if (is64) return (int)((const long long*)ei)[elem];
    return ((const int*)ei)[elem];
}

// block-local edge dtype detection (first 256 u64 words; int64 -> all-zero high words)
__device__ __forceinline__ int detect_is64_block(const void* ei) {
    const ull* p = (const ull*)ei;
    int any = __syncthreads_or((int)((p[threadIdx.x & 255] >> 32) != 0ULL));
    return !any;
}

__device__ __forceinline__ void f4_to_h8(float4 v, uint2& o) {
    __half2 h01 = __floats2half2_rn(v.x, v.y);
    __half2 h23 = __floats2half2_rn(v.z, v.w);
    o.x = *(const u32*)&h01;
    o.y = *(const u32*)&h23;
}

// ============ prep (fat kernel): convert x | convert W | count degrees ========
__global__ void __launch_bounds__(256) prep_kernel(const float* __restrict__ x,
                                                   const float* __restrict__ W1,
                                                   const float* __restrict__ W2,
                                                   const void* __restrict__ ei) {
    int b = blockIdx.x, tid = threadIdx.x;
    if (b < 3125) {
        const float4* X4 = (const float4*)x;
#pragma unroll
        for (int j = 0; j < 4; j++) {
            int i = b * 1024 + tid + 256 * j;
            uint2 o; f4_to_h8(X4[i], o);
            ((uint2*)g_xh)[i] = o;
        }
    } else if (b < 3149) {
        int i = (b - 3125) * 256 + tid;          // [0, 6144)
        if (i < 4096) {
            uint2 o; f4_to_h8(((const float4*)W1)[i], o);
            ((uint2*)g_w1h)[i] = o;
        } else {
            int j = i - 4096;                    // [0, 2048)
            uint2 o; f4_to_h8(((const float4*)W2)[j], o);
            ((uint2*)g_w2h)[j] = o;
        }
    } else {
        int is64 = detect_is64_block(ei);
        int e = (b - 3149) * 256 + tid;          // < 1.6M exactly
        int d = edge_idx(ei, (long long)N_EDGES + e, is64);
        atomicAdd(&CNT(d), 1);
    }
}

// ============ single-pass scan (decoupled lookback) + dinv + cur ==============
__device__ __forceinline__ u32 warp_sum_u32(u32 v) {
    v += __shfl_xor_sync(~0u, v, 16);
    v += __shfl_xor_sync(~0u, v, 8);
    v += __shfl_xor_sync(~0u, v, 4);
    v += __shfl_xor_sync(~0u, v, 2);
    v += __shfl_xor_sync(~0u, v, 1);
    return v;
}

__global__ void __launch_bounds__(512) scan_fused_kernel() {
    __shared__ int wsum[16];
    __shared__ int s_prefix;
    int tile = blockIdx.x, tid = threadIdx.x;
    int lane = tid & 31, w = tid >> 5;
    int i = tile * 512 + tid;
    int v = (i < N_NODES) ? CNT(i) : 0;

    int xv = v;
#pragma unroll
    for (int d = 1; d < 32; d <<= 1) {
        int y = __shfl_up_sync(~0u, xv, d);
        if (lane >= d) xv += y;
    }
    if (lane == 31) wsum[w] = xv;
    __syncthreads();
    if (w == 0) {
        int s = (lane < 16) ? wsum[lane] : 0;
#pragma unroll
        for (int d = 1; d < 16; d <<= 1) {
            int y = __shfl_up_sync(~0u, s, d);
            if (lane >= d) s += y;
        }
        if (lane < 16) wsum[lane] = s;
    }
    __syncthreads();
    int warp_off = w ? wsum[w - 1] : 0;
    int incl = xv + warp_off;
    int total = wsum[15];

    if (w == 0) {
        if (lane == 0)
            atomicExch(&STATUS(tile), (u32)total | (tile == 0 ? FLAG_INC : FLAG_AGG));
        u32 prefix = 0;
        if (tile > 0) {
            int t = tile - 1;
            while (true) {
                int idx = t - lane;
                u32 s = (idx >= 0) ? atomicAdd(&STATUS(idx), 0u) : FLAG_INC;
                if (__ballot_sync(~0u, (s & 0xC0000000u) != 0u) != 0xFFFFFFFFu) continue;
                u32 incmask = __ballot_sync(~0u, (s & FLAG_INC) != 0u);
                if (incmask == 0u) {
                    prefix += warp_sum_u32(s & VALMASK);
                    t -= 32;
                } else {
                    int firstinc = __ffs(incmask) - 1;
                    u32 contrib = (lane <= firstinc) ? (s & VALMASK) : 0u;
                    prefix += warp_sum_u32(contrib);
                    break;
                }
            }
            if (lane == 0) atomicExch(&STATUS(tile), (prefix + (u32)total) | FLAG_INC);
        }
        if (lane == 0) s_prefix = (int)prefix;
    }
    __syncthreads();
    if (i < N_NODES) {
        int off = s_prefix + incl - v;
        g_off[i] = off;
        g_cur[i] = off;
        g_dinv[i] = rsqrtf((float)(v + 1));   // +1 self-loop
    }
}

// ============ bucket edges by dst: write {src, dinv[src] bits} ===============
__global__ void __launch_bounds__(256) bucket_kernel(const void* __restrict__ ei) {
    int is64 = detect_is64_block(ei);
    int e = blockIdx.x * 256 + threadIdx.x;   // < 1.6M exactly
    int s = edge_idx(ei, e, is64);
    int d = edge_idx(ei, (long long)N_EDGES + e, is64);
    float ns = __ldg(g_dinv + s);
    int pos = atomicAdd(&g_cur[d], 1);
    uint2 en; en.x = (u32)s; en.y = __float_as_uint(ns);
    g_epack[pos] = en;
}

// ============ aggregate: one warp per dst node, paired LDG.128 epack =========
__device__ __forceinline__ void acc_half8(float4& acc, uint2 v, float n) {
    float2 f01 = __half22float2(*(__half2*)&v.x);
    float2 f23 = __half22float2(*(__half2*)&v.y);
    acc.x += n * f01.x; acc.y += n * f01.y;
    acc.z += n * f23.x; acc.w += n * f23.y;
}

__global__ void __launch_bounds__(256) aggregate_kernel() {
    int node = blockIdx.x * 8 + (threadIdx.x >> 5);
    if (node >= N_PAD) return;
    int lane = threadIdx.x & 31;
    float4 acc = make_float4(0.f, 0.f, 0.f, 0.f);

    if (node < N_NODES) {
        int beg = g_off[node];
        int end = (node + 1 < N_NODES) ? g_off[node + 1] : N_EDGES;
        float dd = g_dinv[node];

        uint2 sv = __ldg(((const uint2*)g_xh) + (size_t)node * 32 + lane);
        acc_half8(acc, sv, dd * dd);   // self-loop

        int i = beg;
        if (i < end && (i & 1)) {      // align to even index for uint4 loads
            uint2 e0 = __ldg(g_epack + i);
            uint2 v0 = __ldg(((const uint2*)g_xh) + (size_t)e0.x * 32 + lane);
            acc_half8(acc, v0, __uint_as_float(e0.y) * dd);
            i++;
        }
        for (; i + 3 < end; i += 4) {  // 2x LDG.128 -> 4 edges
            uint4 p01 = __ldg((const uint4*)(g_epack + i));
            uint4 p23 = __ldg((const uint4*)(g_epack + i + 2));
            uint2 v0 = __ldg(((const uint2*)g_xh) + (size_t)p01.x * 32 + lane);
            uint2 v1 = __ldg(((const uint2*)g_xh) + (size_t)p01.z * 32 + lane);
            uint2 v2 = __ldg(((const uint2*)g_xh) + (size_t)p23.x * 32 + lane);
            uint2 v3 = __ldg(((const uint2*)g_xh) + (size_t)p23.z * 32 + lane);
            acc_half8(acc, v0, __uint_as_float(p01.y) * dd);
            acc_half8(acc, v1, __uint_as_float(p01.w) * dd);
            acc_half8(acc, v2, __uint_as_float(p23.y) * dd);
            acc_half8(acc, v3, __uint_as_float(p23.w) * dd);
        }
        if (i + 1 < end) {             // one more pair
            uint4 p01 = __ldg((const uint4*)(g_epack + i));
            uint2 v0 = __ldg(((const uint2*)g_xh) + (size_t)p01.x * 32 + lane);
            uint2 v1 = __ldg(((const uint2*)g_xh) + (size_t)p01.z * 32 + lane);
            acc_half8(acc, v0, __uint_as_float(p01.y) * dd);
            acc_half8(acc, v1, __uint_as_float(p01.w) * dd);
            i += 2;
        }
        if (i < end) {                 // tail single
            uint2 e0 = __ldg(g_epack + i);
            uint2 v0 = __ldg(((const uint2*)g_xh) + (size_t)e0.x * 32 + lane);
            acc_half8(acc, v0, __uint_as_float(e0.y) * dd);
        }
    }
    __half2 h01 = __floats2half2_rn(acc.x, acc.y);
    __half2 h23 = __floats2half2_rn(acc.z, acc.w);
    uint2 o;
    o.x = *(const u32*)&h01;
    o.y = *(const u32*)&h23;
    ((uint2*)g_axh)[(size_t)node * 32 + lane] = o;
}

// -------- persistent fused tensor-core GEMM ---------------------------------
#define AS 136   // padded row stride (halfs) for 128-wide tiles
#define WS2 72   // padded row stride for 64-wide W2 tile

__global__ void __launch_bounds__(512, 2) fused_mma_kernel(const float* __restrict__ b1,
                                                           const float* __restrict__ b2,
                                                           float* __restrict__ out) {
    extern __shared__ __half smh[];
    __half* sW1 = smh;                 // 128 x AS
    __half* sW2 = sW1 + 128 * AS;      // 128 x WS2
    __half* sA  = sW2 + 128 * WS2;     // 128 x AS  (reused as T tile)
    __half* sT  = sA;                  // alias

    int tid = threadIdx.x;
    int warp = tid >> 5, lane = tid & 31;
    int nr = (warp & 7) * 16;
    int colq = 2 * (lane & 3);
    int rq = lane >> 2;

    // ---- load W tiles once ----
    {
        const uint4* W14 = (const uint4*)g_w1h;
#pragma unroll
        for (int i = 0; i < 4; i++) {
            int idx = tid + 512 * i;
            int row = idx >> 4, c = idx & 15;
            CP_ASYNC16(smaddr(sW1 + row * AS + c * 8), W14 + idx);
        }
        const uint4* W24 = (const uint4*)g_w2h;
#pragma unroll
        for (int i = 0; i < 2; i++) {
            int idx = tid + 512 * i;
            int row = idx >> 3, c = idx & 7;
            CP_ASYNC16(smaddr(sW2 + row * WS2 + c * 8), W24 + idx);
        }
        CP_ASYNC_COMMIT();
    }

    for (int tile = blockIdx.x; tile < N_TILES; tile += MMA_GRID) {
        int base = tile * 128;

        {
            const uint4* A4 = (const uint4*)(g_axh + (size_t)base * 128);
#pragma unroll
            for (int i = 0; i < 4; i++) {
                int idx = tid + 512 * i;
                int row = idx >> 4, c = idx & 15;
                CP_ASYNC16(smaddr(sA + row * AS + c * 8), A4 + idx);
            }
            CP_ASYNC_COMMIT();
            CP_ASYNC_WAIT0();
        }
        __syncthreads();

        // ---- stage 1: acc = sA @ W1 ----
        float acc1[8][4];
        {
            int cb = (warp >> 3) * 64;
#pragma unroll
            for (int t = 0; t < 8; t++)
#pragma unroll
                for (int j = 0; j < 4; j++) acc1[t][j] = 0.f;

            u32 aAbase = smaddr(sA + (nr + (lane & 15)) * AS + ((lane >> 4) * 8));
            u32 aBbase = smaddr(sW1 + (lane & 15) * AS + cb);

#pragma unroll
            for (int ks = 0; ks < 8; ks++) {
                u32 a0, a1, a2, a3;
                LDSM4(a0, a1, a2, a3, aAbase + ks * 32);
#pragma unroll
                for (int nt = 0; nt < 8; nt++) {
                    u32 b0, b1r;
                    LDSM2T(b0, b1r, aBbase + ks * 16 * AS * 2 + nt * 16);
                    MMA16816(acc1[nt], a0, a1, a2, a3, b0, b1r);
                }
            }
        }
        __syncthreads();   // all stage-1 reads of sA complete

        // ---- epilogue 1: T = relu(acc + b1) written over sA ----
        {
            int cb = (warp >> 3) * 64;
#pragma unroll
            for (int nt = 0; nt < 8; nt++) {
                int c0 = cb + nt * 8 + colq;
                float2 bv = __ldg((const float2*)(b1 + c0));
                int r0 = nr + rq;
                __half2 h0 = __floats2half2_rn(fmaxf(acc1[nt][0] + bv.x, 0.f),
                                               fmaxf(acc1[nt][1] + bv.y, 0.f));
                __half2 h1 = __floats2half2_rn(fmaxf(acc1[nt][2] + bv.x, 0.f),
                                               fmaxf(acc1[nt][3] + bv.y, 0.f));
                *(__half2*)(sT + r0 * AS + c0) = h0;
                *(__half2*)(sT + (r0 + 8) * AS + c0) = h1;
            }
        }
        __syncthreads();

        // ---- stage 2: out = T @ W2 + b2 ----
        {
            int cb = (warp >> 3) * 32;
            float acc[4][4];
#pragma unroll
            for (int t = 0; t < 4; t++)
#pragma unroll
                for (int j = 0; j < 4; j++) acc[t][j] = 0.f;

            u32 aAbase = smaddr(sT + (nr + (lane & 15)) * AS + ((lane >> 4) * 8));
            u32 aBbase = smaddr(sW2 + (lane & 15) * WS2 + cb);

#pragma unroll
            for (int ks = 0; ks < 8; ks++) {
                u32 a0, a1, a2, a3;
                LDSM4(a0, a1, a2, a3, aAbase + ks * 32);
#pragma unroll
                for (int nt = 0; nt < 4; nt++) {
                    u32 b0, b1r;
                    LDSM2T(b0, b1r, aBbase + ks * 16 * WS2 * 2 + nt * 16);
                    MMA16816(acc[nt], a0, a1, a2, a3, b0, b1r);
                }
            }

#pragma unroll
            for (int nt = 0; nt < 4; nt++) {
                int c0 = cb + nt * 8 + colq;
                float2 bv = __ldg((const float2*)(b2 + c0));
                int n0 = base + nr + rq;
                int n1 = n0 + 8;
                if (n0 < N_NODES) {
                    float2 r = make_float2(acc[nt][0] + bv.x, acc[nt][1] + bv.y);
                    *(float2*)(out + (size_t)n0 * OUT_DIM + c0) = r;
                }
                if (n1 < N_NODES) {
                    float2 r = make_float2(acc[nt][2] + bv.x, acc[nt][3] + bv.y);
                    *(float2*)(out + (size_t)n1 * OUT_DIM + c0) = r;
                }
            }
        }
        __syncthreads();   // stage-2 reads of sT done before next tile overwrites sA
    }
}

extern "C" void kernel_launch(void* const* d_in, const int* in_sizes, int n_in,
                              void* d_out, int out_size) {
    const float* x  = (const float*)d_in[0];
    const float* W1 = (const float*)d_in[1];
    const float* b1 = (const float*)d_in[2];
    const float* W2 = (const float*)d_in[3];
    const float* b2 = (const float*)d_in[4];
    const void*  ei = d_in[5];
    float* out = (float*)d_out;

    const int FUSED_SMEM = (2 * 128 * AS + 128 * WS2) * 2;   // 88064 B
    cudaFuncSetAttribute(fused_mma_kernel, cudaFuncAttributeMaxDynamicSharedMemorySize, FUSED_SMEM);

    void* zero_ptr = nullptr;
    cudaGetSymbolAddress(&zero_ptr, g_zero_blob);
    cudaMemsetAsync(zero_ptr, 0, (N_NODES + 256) * sizeof(int));

    prep_kernel<<<3125 + 24 + 6250, 256>>>(x, W1, W2, ei);
    scan_fused_kernel<<<SCAN_TILES, 512>>>();
    bucket_kernel<<<N_EDGES / 256, 256>>>(ei);
    aggregate_kernel<<<N_PAD / 8, 256>>>();
    fused_mma_kernel<<<MMA_GRID, 512, FUSED_SMEM>>>(b1, b2, out);
}

// round 15
// speedup vs baseline: 1.0655x; 1.0311x over previous
#include <cuda_runtime.h>
#include <cuda_fp16.h>
#include <cstdint>

#define N_NODES 100000
#define N_PAD   100096          // multiple of 128 for fused gemm tiles
#define N_EDGES 1600000
#define IN_DIM 128
#define HIDDEN 128
#define OUT_DIM 64

#define SCAN_TILES 196          // ceil(100000/512)
#define N_TILES (N_PAD / 128)   // 782
#define MMA_GRID 296            // 2 CTAs/SM * 148 SMs

typedef unsigned long long ull;
typedef unsigned int u32;

// -------- scratch (static device globals; no allocation allowed) --------
__device__ __align__(16) __half g_xh[(size_t)N_NODES * IN_DIM];   // x in fp16
__device__ __align__(16) __half g_axh[(size_t)N_PAD * IN_DIM];    // A_norm @ x, fp16
__device__ __align__(16) __half g_w1h[IN_DIM * HIDDEN];
__device__ __align__(16) __half g_w2h[HIDDEN * OUT_DIM];
__device__ float g_dinv[N_NODES];
// zero blob: [0, N_NODES) = per-node incoming counts ; [N_NODES, +256) = scan status
__device__ int   g_zero_blob[N_NODES + 256];
__device__ int   g_off[N_NODES];
__device__ int   g_cur[N_NODES];
__device__ __align__(16) uint2 g_epack[N_EDGES];   // {src, dinv[src] bits}

#define CNT(i)    (g_zero_blob[i])
#define STATUS(t) (((u32*)g_zero_blob)[N_NODES + (t)])
#define FLAG_AGG 0x40000000u
#define FLAG_INC 0x80000000u
#define VALMASK  0x3FFFFFFFu

// -------- mma / ldmatrix / cp.async helpers --------
#define LDSM4(a0,a1,a2,a3,addr) \
    asm volatile("ldmatrix.sync.aligned.m8n8.x4.shared.b16 {%0,%1,%2,%3},[%4];" \
                 : "=r"(a0),"=r"(a1),"=r"(a2),"=r"(a3) : "r"(addr))
#define LDSM2T(b0,b1,addr) \
    asm volatile("ldmatrix.sync.aligned.m8n8.x2.trans.shared.b16 {%0,%1},[%2];" \
                 : "=r"(b0),"=r"(b1) : "r"(addr))
#define MMA16816(d,a0,a1,a2,a3,b0,b1) \
    asm volatile("mma.sync.aligned.m16n8k16.row.col.f32.f16.f16.f32 " \
                 "{%0,%1,%2,%3},{%4,%5,%6,%7},{%8,%9},{%0,%1,%2,%3};" \
                 : "+f"((d)[0]),"+f"((d)[1]),"+f"((d)[2]),"+f"((d)[3]) \
                 : "r"(a0),"r"(a1),"r"(a2),"r"(a3),"r"(b0),"r"(b1))
#define CP_ASYNC16(saddr, gptr) \
    asm volatile("cp.async.cg.shared.global [%0], [%1], 16;" :: "r"(saddr), "l"(gptr))
#define CP_ASYNC_COMMIT() asm volatile("cp.async.commit_group;")
#define CP_ASYNC_WAIT0()  asm volatile("cp.async.wait_group 0;")

__device__ __forceinline__ u32 smaddr(const void* p) {
    return (u32)__cvta_generic_to_shared(p);
}

__device__ __forceinline__ int edge_idx(const void* ei, long long elem, int is64) {
    if (is64) return (int)((const long long*)ei)[elem];
    return ((const int*)ei)[elem];
}

// block-local edge dtype detection (first 256 u64 words; int64 -> all-zero high words)
__device__ __forceinline__ int detect_is64_block(const void* ei) {
    const ull* p = (const ull*)ei;
    int any = __syncthreads_or((int)((p[threadIdx.x & 255] >> 32) != 0ULL));
    return !any;
}

__device__ __forceinline__ void f4_to_h8(float4 v, uint2& o) {
    __half2 h01 = __floats2half2_rn(v.x, v.y);
    __half2 h23 = __floats2half2_rn(v.z, v.w);
    o.x = *(const u32*)&h01;
    o.y = *(const u32*)&h23;
}

__device__ __forceinline__ u32 packh2(float a, float b) {
    __half2 h = __floats2half2_rn(a, b);
    return *(const u32*)&h;
}

// ============ prep (fat kernel): convert x | convert W | count degrees ========
__global__ void __launch_bounds__(256) prep_kernel(const float* __restrict__ x,
                                                   const float* __restrict__ W1,
                                                   const float* __restrict__ W2,
                                                   const void* __restrict__ ei) {
    int b = blockIdx.x, tid = threadIdx.x;
    if (b < 3125) {
        const float4* X4 = (const float4*)x;
#pragma unroll
        for (int j = 0; j < 4; j++) {
            int i = b * 1024 + tid + 256 * j;
            uint2 o; f4_to_h8(X4[i], o);
            ((uint2*)g_xh)[i] = o;
        }
    } else if (b < 3149) {
        int i = (b - 3125) * 256 + tid;          // [0, 6144)
        if (i < 4096) {
            uint2 o; f4_to_h8(((const float4*)W1)[i], o);
            ((uint2*)g_w1h)[i] = o;
        } else {
            int j = i - 4096;                    // [0, 2048)
            uint2 o; f4_to_h8(((const float4*)W2)[j], o);
            ((uint2*)g_w2h)[j] = o;
        }
    } else {
        int is64 = detect_is64_block(ei);
        int e = (b - 3149) * 256 + tid;          // < 1.6M exactly
        int d = edge_idx(ei, (long long)N_EDGES + e, is64);
        atomicAdd(&CNT(d), 1);
    }
}

// ============ single-pass scan (decoupled lookback) + dinv + cur ==============
__device__ __forceinline__ u32 warp_sum_u32(u32 v) {
    v += __shfl_xor_sync(~0u, v, 16);
    v += __shfl_xor_sync(~0u, v, 8);
    v += __shfl_xor_sync(~0u, v, 4);
    v += __shfl_xor_sync(~0u, v, 2);
    v += __shfl_xor_sync(~0u, v, 1);
    return v;
}

__global__ void __launch_bounds__(512) scan_fused_kernel() {
    __shared__ int wsum[16];
    __shared__ int s_prefix;
    int tile = blockIdx.x, tid = threadIdx.x;
    int lane = tid & 31, w = tid >> 5;
    int i = tile * 512 + tid;
    int v = (i < N_NODES) ? CNT(i) : 0;

    int xv = v;
#pragma unroll
    for (int d = 1; d < 32; d <<= 1) {
        int y = __shfl_up_sync(~0u, xv, d);
        if (lane >= d) xv += y;
    }
    if (lane == 31) wsum[w] = xv;
    __syncthreads();
    if (w == 0) {
        int s = (lane < 16) ? wsum[lane] : 0;
#pragma unroll
        for (int d = 1; d < 16; d <<= 1) {
            int y = __shfl_up_sync(~0u, s, d);
            if (lane >= d) s += y;
        }
        if (lane < 16) wsum[lane] = s;
    }
    __syncthreads();
    int warp_off = w ? wsum[w - 1] : 0;
    int incl = xv + warp_off;
    int total = wsum[15];

    if (w == 0) {
        if (lane == 0)
            atomicExch(&STATUS(tile), (u32)total | (tile == 0 ? FLAG_INC : FLAG_AGG));
        u32 prefix = 0;
        if (tile > 0) {
            int t = tile - 1;
            while (true) {
                int idx = t - lane;
                u32 s = (idx >= 0) ? atomicAdd(&STATUS(idx), 0u) : FLAG_INC;
                if (__ballot_sync(~0u, (s & 0xC0000000u) != 0u) != 0xFFFFFFFFu) continue;
                u32 incmask = __ballot_sync(~0u, (s & FLAG_INC) != 0u);
                if (incmask == 0u) {
                    prefix += warp_sum_u32(s & VALMASK);
                    t -= 32;
                } else {
                    int firstinc = __ffs(incmask) - 1;
                    u32 contrib = (lane <= firstinc) ? (s & VALMASK) : 0u;
                    prefix += warp_sum_u32(contrib);
                    break;
                }
            }
            if (lane == 0) atomicExch(&STATUS(tile), (prefix + (u32)total) | FLAG_INC);
        }
        if (lane == 0) s_prefix = (int)prefix;
    }
    __syncthreads();
    if (i < N_NODES) {
        int off = s_prefix + incl - v;
        g_off[i] = off;
        g_cur[i] = off;
        g_dinv[i] = rsqrtf((float)(v + 1));   // +1 self-loop
    }
}

// ============ bucket edges by dst: write {src, dinv[src] bits} ===============
__global__ void __launch_bounds__(256) bucket_kernel(const void* __restrict__ ei) {
    int is64 = detect_is64_block(ei);
    int e = blockIdx.x * 256 + threadIdx.x;   // < 1.6M exactly
    int s = edge_idx(ei, e, is64);
    int d = edge_idx(ei, (long long)N_EDGES + e, is64);
    float ns = __ldg(g_dinv + s);
    int pos = atomicAdd(&g_cur[d], 1);
    uint2 en; en.x = (u32)s; en.y = __float_as_uint(ns);
    g_epack[pos] = en;
}

// ============ aggregate: one warp per dst node (R12 winner, untouched) =======
__device__ __forceinline__ void acc_half8(float4& acc, uint2 v, float n) {
    float2 f01 = __half22float2(*(__half2*)&v.x);
    float2 f23 = __half22float2(*(__half2*)&v.y);
    acc.x += n * f01.x; acc.y += n * f01.y;
    acc.z += n * f23.x; acc.w += n * f23.y;
}

__global__ void __launch_bounds__(256) aggregate_kernel() {
    int node = blockIdx.x * 8 + (threadIdx.x >> 5);
    if (node >= N_PAD) return;
    int lane = threadIdx.x & 31;
    float4 acc = make_float4(0.f, 0.f, 0.f, 0.f);

    if (node < N_NODES) {
        int beg = g_off[node];
        int end = (node + 1 < N_NODES) ? g_off[node + 1] : N_EDGES;
        float dd = g_dinv[node];

        uint2 sv = __ldg(((const uint2*)g_xh) + (size_t)node * 32 + lane);
        acc_half8(acc, sv, dd * dd);   // self-loop

        int i = beg;
        for (; i + 3 < end; i += 4) {
            uint2 e0 = __ldg(g_epack + i);
            uint2 e1 = __ldg(g_epack + i + 1);
            uint2 e2 = __ldg(g_epack + i + 2);
            uint2 e3 = __ldg(g_epack + i + 3);
            uint2 v0 = __ldg(((const uint2*)g_xh) + (size_t)e0.x * 32 + lane);
            uint2 v1 = __ldg(((const uint2*)g_xh) + (size_t)e1.x * 32 + lane);
            uint2 v2 = __ldg(((const uint2*)g_xh) + (size_t)e2.x * 32 + lane);
            uint2 v3 = __ldg(((const uint2*)g_xh) + (size_t)e3.x * 32 + lane);
            acc_half8(acc, v0, __uint_as_float(e0.y) * dd);
            acc_half8(acc, v1, __uint_as_float(e1.y) * dd);
            acc_half8(acc, v2, __uint_as_float(e2.y) * dd);
            acc_half8(acc, v3, __uint_as_float(e3.y) * dd);
        }
        for (; i < end; i++) {
            uint2 e0 = __ldg(g_epack + i);
            uint2 v0 = __ldg(((const uint2*)g_xh) + (size_t)e0.x * 32 + lane);
            acc_half8(acc, v0, __uint_as_float(e0.y) * dd);
        }
    }
    __half2 h01 = __floats2half2_rn(acc.x, acc.y);
    __half2 h23 = __floats2half2_rn(acc.z, acc.w);
    uint2 o;
    o.x = *(const u32*)&h01;
    o.y = *(const u32*)&h23;
    ((uint2*)g_axh)[(size_t)node * 32 + lane] = o;
}

// -------- persistent fused tensor-core GEMM, register-fragment stage 2 ------
// warp (r = w&7, kc = w>>3): stage1 computes T-half = relu(A@W1+b1) for nodes
// [16r,16r+16) x cols [64kc, 64kc+64) kept in REGISTERS (C-frag == A-frag
// identity). stage2: partial out over its K-half; kc=1 ships fp16 partial via
// 16KB smem buffer; kc=0 reduces + writes. sA freed between barriers -> next
// tile's A cp.async overlaps stage 2.
#define AS 136   // padded row stride (halfs) for 128-wide tiles
#define WS2 72   // padded row stride for 64-wide W2 tile

__global__ void __launch_bounds__(512, 2) fused_mma_kernel(const float* __restrict__ b1,
                                                           const float* __restrict__ b2,
                                                           float* __restrict__ out) {
    extern __shared__ __half smh[];
    __half* sW1  = smh;                  // 128 x AS
    __half* sW2  = sW1 + 128 * AS;       // 128 x WS2
    __half* sA   = sW2 + 128 * WS2;      // 128 x AS
    __half* sRed = sA + 128 * AS;        // 8 pairs x 1024 halfs = 16 KB

    int tid = threadIdx.x;
    int warp = tid >> 5, lane = tid & 31;
    int r = warp & 7, kc = warp >> 3;
    int nr = r * 16;
    int colq = 2 * (lane & 3);
    int rq = lane >> 2;

    // ---- load W tiles once ----
    {
        const uint4* W14 = (const uint4*)g_w1h;
#pragma unroll
        for (int i = 0; i < 4; i++) {
            int idx = tid + 512 * i;
            int row = idx >> 4, c = idx & 15;
            CP_ASYNC16(smaddr(sW1 + row * AS + c * 8), W14 + idx);
        }
        const uint4* W24 = (const uint4*)g_w2h;
#pragma unroll
        for (int i = 0; i < 2; i++) {
            int idx = tid + 512 * i;
            int row = idx >> 3, c = idx & 7;
            CP_ASYNC16(smaddr(sW2 + row * WS2 + c * 8), W24 + idx);
        }
    }
    // ---- load first A tile ----
    {
        const uint4* A4 = (const uint4*)(g_axh + (size_t)blockIdx.x * 128 * 128);
#pragma unroll
        for (int i = 0; i < 4; i++) {
            int idx = tid + 512 * i;
            int row = idx >> 4, c = idx & 15;
            CP_ASYNC16(smaddr(sA + row * AS + c * 8), A4 + idx);
        }
        CP_ASYNC_COMMIT();
        CP_ASYNC_WAIT0();
    }
    __syncthreads();

    for (int tile = blockIdx.x; tile < N_TILES; tile += MMA_GRID) {
        int base = tile * 128;

        // ---- stage 1: acc1 = sA @ W1 (this warp's 64-col half) ----
        float acc1[8][4];
        {
#pragma unroll
            for (int t = 0; t < 8; t++)
#pragma unroll
                for (int j = 0; j < 4; j++) acc1[t][j] = 0.f;

            u32 aAbase = smaddr(sA + (nr + (lane & 15)) * AS + ((lane >> 4) * 8));
            u32 aBbase = smaddr(sW1 + (lane & 15) * AS + kc * 64);

#pragma unroll
            for (int ks = 0; ks < 8; ks++) {
                u32 a0, a1, a2, a3;
                LDSM4(a0, a1, a2, a3, aAbase + ks * 32);
#pragma unroll
                for (int nt = 0; nt < 8; nt++) {
                    u32 b0, b1r;
                    LDSM2T(b0, b1r, aBbase + ks * 16 * AS * 2 + nt * 16);
                    MMA16816(acc1[nt], a0, a1, a2, a3, b0, b1r);
                }
            }
        }

        // ---- convert to A-fragments with bias + relu (registers only) ----
        u32 afrag[4][4];
#pragma unroll
        for (int p = 0; p < 4; p++) {
            int nt0 = 2 * p, nt1 = 2 * p + 1;
            float2 bv0 = __ldg((const float2*)(b1 + kc * 64 + nt0 * 8 + colq));
            float2 bv1 = __ldg((const float2*)(b1 + kc * 64 + nt1 * 8 + colq));
            afrag[p][0] = packh2(fmaxf(acc1[nt0][0] + bv0.x, 0.f),
                                 fmaxf(acc1[nt0][1] + bv0.y, 0.f));
            afrag[p][1] = packh2(fmaxf(acc1[nt0][2] + bv0.x, 0.f),
                                 fmaxf(acc1[nt0][3] + bv0.y, 0.f));
            afrag[p][2] = packh2(fmaxf(acc1[nt1][0] + bv1.x, 0.f),
                                 fmaxf(acc1[nt1][1] + bv1.y, 0.f));
            afrag[p][3] = packh2(fmaxf(acc1[nt1][2] + bv1.x, 0.f),
                                 fmaxf(acc1[nt1][3] + bv1.y, 0.f));
        }
        __syncthreads();   // all stage-1 reads of sA complete

        // ---- prefetch next A tile into sA (overlaps stage 2) ----
        {
            int ntile = tile + MMA_GRID;
            if (ntile < N_TILES) {
                const uint4* A4 = (const uint4*)(g_axh + (size_t)ntile * 128 * 128);
#pragma unroll
                for (int i = 0; i < 4; i++) {
                    int idx = tid + 512 * i;
                    int row = idx >> 4, c = idx & 15;
                    CP_ASYNC16(smaddr(sA + row * AS + c * 8), A4 + idx);
                }
            }
            CP_ASYNC_COMMIT();
        }

        // ---- stage 2: partial out = T_half @ W2[K-half] ----
        float pacc[8][4];
#pragma unroll
        for (int t = 0; t < 8; t++)
#pragma unroll
            for (int j = 0; j < 4; j++) pacc[t][j] = 0.f;
        {
            u32 bBase2 = smaddr(sW2 + (kc * 64 + (lane & 15)) * WS2);
#pragma unroll
            for (int p = 0; p < 4; p++) {
#pragma unroll
                for (int nt = 0; nt < 8; nt++) {
                    u32 b0, b1r;
                    LDSM2T(b0, b1r, bBase2 + p * 16 * WS2 * 2 + nt * 16);
                    MMA16816(pacc[nt], afrag[p][0], afrag[p][1],
                             afrag[p][2], afrag[p][3], b0, b1r);
                }
            }
        }

        // ---- reduction: kc=1 ships fp16 partial, kc=0 adds + writes ----
        __half* myb = sRed + r * 1024;
        if (kc == 1) {
#pragma unroll
            for (int nt = 0; nt < 8; nt++) {
                uint2 q;
                q.x = packh2(pacc[nt][0], pacc[nt][1]);
                q.y = packh2(pacc[nt][2], pacc[nt][3]);
                *(uint2*)(myb + nt * 128 + lane * 4) = q;
            }
        }
        __syncthreads();
        if (kc == 0) {
            int n0 = base + nr + rq;
            int n1 = n0 + 8;
#pragma unroll
            for (int nt = 0; nt < 8; nt++) {
                uint2 q = *(uint2*)(myb + nt * 128 + lane * 4);
                float2 f01 = __half22float2(*(__half2*)&q.x);
                float2 f23 = __half22float2(*(__half2*)&q.y);
                float2 bv = __ldg((const float2*)(b2 + nt * 8 + colq));
                if (n0 < N_NODES) {
                    float2 o0 = make_float2(pacc[nt][0] + f01.x + bv.x,
                                            pacc[nt][1] + f01.y + bv.y);
                    *(float2*)(out + (size_t)n0 * OUT_DIM + nt * 8 + colq) = o0;
                }
                if (n1 < N_NODES) {
                    float2 o1 = make_float2(pacc[nt][2] + f23.x + bv.x,
                                            pacc[nt][3] + f23.y + bv.y);
                    *(float2*)(out + (size_t)n1 * OUT_DIM + nt * 8 + colq) = o1;
                }
            }
        }
        CP_ASYNC_WAIT0();
        __syncthreads();   // next A tile resident; sRed reads complete
    }
}

extern "C" void kernel_launch(void* const* d_in, const int* in_sizes, int n_in,
                              void* d_out, int out_size) {
    const float* x  = (const float*)d_in[0];
    const float* W1 = (const float*)d_in[1];
    const float* b1 = (const float*)d_in[2];
    const float* W2 = (const float*)d_in[3];
    const float* b2 = (const float*)d_in[4];
    const void*  ei = d_in[5];
    float* out = (float*)d_out;

    const int FUSED_SMEM = (2 * 128 * AS + 128 * WS2) * 2 + 16384;   // 104448 B
    cudaFuncSetAttribute(fused_mma_kernel, cudaFuncAttributeMaxDynamicSharedMemorySize, FUSED_SMEM);

    void* zero_ptr = nullptr;
    cudaGetSymbolAddress(&zero_ptr, g_zero_blob);
    cudaMemsetAsync(zero_ptr, 0, (N_NODES + 256) * sizeof(int));

    prep_kernel<<<3125 + 24 + 6250, 256>>>(x, W1, W2, ei);
    scan_fused_kernel<<<SCAN_TILES, 512>>>();
    bucket_kernel<<<N_EDGES / 256, 256>>>(ei);
    aggregate_kernel<<<N_PAD / 8, 256>>>();
    fused_mma_kernel<<<MMA_GRID, 512, FUSED_SMEM>>>(b1, b2, out);
}